// round 10
// baseline (speedup 1.0000x reference)
#include <cuda_runtime.h>
#include <cstdint>

#define M_R   12
#define N_E   8
#define C_DIM 1024
#define D_DIM 64
#define B_DIM 32
#define S_DIM 512
#define TS    128
#define THREADS 128

// smem pitches (words). Bank math (32 banks):
//  A frags (32-wide): pitch 36 -> bank = (4*gr + gc) & 31, distinct over 32 lanes
//  W frags:           pitch 72 -> bank = (8*gc + gr) & 31, distinct
//  Z frags (64-wide): pitch 68 -> bank = (4*gr + gc) & 31, distinct   [64 cols NEED pitch>=64]
#define PA 36
#define PW 72
#define PZ 68

// dynamic smem byte offsets
// Phase 1 peak: SA0+SA1+SW0+SW1 = 55296
// Phase 2 peak: ZB(34816) + W2(18432) = 53248  (ZB overlays SA0/SA1, W2 overlays SW0/SW1)
#define SA0 0                         // X stage 0: 128*36*4 = 18432
#define SA1 18432                     // X stage 1
#define SW0 36864                     // Wd stage 0: 32*72*4 = 9216
#define SW1 46080                     // Wd stage 1 (ends 55296)
#define ZB  0                         // Z buffer: 128*68*4 = 34816
#define W2  36864                     // Wu single stage: 64*72*4 = 18432 (ends 55296)
#define SMEM_BYTES 55552

__device__ __forceinline__ uint32_t smem_u32(const void* p) {
    uint32_t a;
    asm("{ .reg .u64 t; cvta.to.shared.u64 t, %1; cvt.u32.u64 %0, t; }" : "=r"(a) : "l"(p));
    return a;
}
__device__ __forceinline__ uint32_t f2tf32(float f) {
    uint32_t u; asm("cvt.rna.tf32.f32 %0, %1;" : "=r"(u) : "f"(f)); return u;
}
__device__ __forceinline__ void cp16(uint32_t dst, const void* src) {
    asm volatile("cp.async.ca.shared.global [%0], [%1], 16;" :: "r"(dst), "l"(src));
}
#define CP_COMMIT() asm volatile("cp.async.commit_group;" ::: "memory")
#define CP_WAIT0()  asm volatile("cp.async.wait_group 0;" ::: "memory")
#define CP_WAIT1()  asm volatile("cp.async.wait_group 1;" ::: "memory")

__device__ __forceinline__ void mma_tf32(float c[4], const uint32_t a[4],
                                         uint32_t b0, uint32_t b1) {
    asm volatile(
        "mma.sync.aligned.m16n8k8.row.col.f32.tf32.tf32.f32 "
        "{%0,%1,%2,%3}, {%4,%5,%6,%7}, {%8,%9}, {%0,%1,%2,%3};\n"
        : "+f"(c[0]), "+f"(c[1]), "+f"(c[2]), "+f"(c[3])
        : "r"(a[0]), "r"(a[1]), "r"(a[2]), "r"(a[3]), "r"(b0), "r"(b1));
}

__global__ __launch_bounds__(THREADS, 4)
void adapter_kernel(const float* __restrict__ x,
                    const int*   __restrict__ eidx,
                    const float* __restrict__ dw,
                    const float* __restrict__ db,
                    const float* __restrict__ uw,
                    float*       __restrict__ out) {
    extern __shared__ float smf[];
    const uint32_t smb = smem_u32(smf);
    __shared__ float sBias[D_DIM];

    const int tid  = threadIdx.x;
    const int lane = tid & 31;
    const int warp = tid >> 5;
    const int gr   = lane >> 2;         // groupID (row within frag)
    const int gc   = lane & 3;          // thread in group (k/col)
    const int wr   = (warp & 1) * 64;   // warp row offset: 64-row tiles
    const int wc   = (warp >> 1) * 32;  // warp col offset: 32-col tiles

    const int m   = blockIdx.x;         // m fastest -> X tile L2-resident across m
    const int bst = blockIdx.y;
    const int b   = bst >> 2;
    const int st  = bst & 3;

    const int e = eidx[m * B_DIM + b];
    const float* xT = x  + ((size_t)b * S_DIM + (size_t)st * TS) * C_DIM;
    const float* wd = dw + (size_t)(m * N_E + e) * C_DIM * D_DIM;
    const float* wu = uw + (size_t)(m * N_E + e) * D_DIM * C_DIM;
    const float* bb = db + (size_t)(m * N_E + e) * D_DIM;
    float* oT = out + (((size_t)m * B_DIM + b) * S_DIM + (size_t)st * TS) * C_DIM;

    if (tid < D_DIM) sBias[tid] = bb[tid];

    float acc[4][4][4];
#pragma unroll
    for (int mi = 0; mi < 4; ++mi)
#pragma unroll
        for (int ni = 0; ni < 4; ++ni)
#pragma unroll
            for (int j = 0; j < 4; ++j) acc[mi][ni][j] = 0.f;

    // -------- prefetch chunk 0 (raw fp32 via cp.async) --------
    {
#pragma unroll
        for (int i = 0; i < 8; ++i) {       // X [128 rows x 32 k]
            int lin = i * 128 + tid, row = lin >> 3, q = (lin & 7) << 2;
            cp16(smb + SA0 + (uint32_t)(row * PA + q) * 4, xT + (size_t)row * C_DIM + q);
        }
#pragma unroll
        for (int i = 0; i < 4; ++i) {       // Wd [32 k x 64 d]
            int lin = i * 128 + tid, kr = lin >> 4, q = (lin & 15) << 2;
            cp16(smb + SW0 + (uint32_t)(kr * PW + q) * 4, wd + (size_t)kr * D_DIM + q);
        }
        CP_COMMIT();
    }

    // ================= Phase 1: D1 = X @ Wd  (32 k-chunks of 32) =================
    for (int kc = 0; kc < 32; ++kc) {
        const int cur = kc & 1;
        const float* sA = smf + (cur ? SA1 : SA0) / 4;
        const float* sW = smf + (cur ? SW1 : SW0) / 4;
        if (kc < 31) {
            const int k0 = (kc + 1) * 32;
            const uint32_t na = smb + (cur ? SA0 : SA1);
            const uint32_t nw = smb + (cur ? SW0 : SW1);
#pragma unroll
            for (int i = 0; i < 8; ++i) {
                int lin = i * 128 + tid, row = lin >> 3, q = (lin & 7) << 2;
                cp16(na + (uint32_t)(row * PA + q) * 4, xT + (size_t)row * C_DIM + k0 + q);
            }
#pragma unroll
            for (int i = 0; i < 4; ++i) {
                int lin = i * 128 + tid, kr = lin >> 4, q = (lin & 15) << 2;
                cp16(nw + (uint32_t)(kr * PW + q) * 4, wd + (size_t)(k0 + kr) * D_DIM + q);
            }
            CP_COMMIT();
            CP_WAIT1();
        } else {
            CP_WAIT0();
        }
        __syncthreads();
#pragma unroll
        for (int kk = 0; kk < 4; ++kk) {
            const int kb = kk * 8;
            uint32_t a[4][4];
#pragma unroll
            for (int mi = 0; mi < 4; ++mi) {
                const float* ap = sA + (wr + mi * 16 + gr) * PA + kb + gc;
                a[mi][0] = f2tf32(ap[0]);
                a[mi][1] = f2tf32(ap[8 * PA]);
                a[mi][2] = f2tf32(ap[4]);
                a[mi][3] = f2tf32(ap[8 * PA + 4]);
            }
#pragma unroll
            for (int ni = 0; ni < 4; ++ni) {
                const float* bp = sW + (kb + gc) * PW + wc + ni * 8 + gr;
                uint32_t b0 = f2tf32(bp[0]);
                uint32_t b1 = f2tf32(bp[4 * PW]);
#pragma unroll
                for (int mi = 0; mi < 4; ++mi) mma_tf32(acc[mi][ni], a[mi], b0, b1);
            }
        }
        __syncthreads();
    }

    // prefetch Wu chunk 0 into W2 (overlays dead Wd stages) while epilogue runs
    {
#pragma unroll
        for (int i = 0; i < 8; ++i) {       // Wu [64 d x 64 c]
            int lin = i * 128 + tid, kr = lin >> 4, q = (lin & 15) << 2;
            cp16(smb + W2 + (uint32_t)(kr * PW + q) * 4, wu + (size_t)kr * C_DIM + q);
        }
        CP_COMMIT();
    }

    // ---- epilogue: Z = swish(D1 + bias) -> zbuf (tf32, pitch 68, overlays SA0/SA1) --
    uint32_t* zb = (uint32_t*)smf;
#pragma unroll
    for (int mi = 0; mi < 4; ++mi)
#pragma unroll
        for (int ni = 0; ni < 4; ++ni) {
            int r = wr + mi * 16 + gr;
            int n = wc + ni * 8 + (gc << 1);
            float z0 = acc[mi][ni][0] + sBias[n];
            float z1 = acc[mi][ni][1] + sBias[n + 1];
            float z2 = acc[mi][ni][2] + sBias[n];
            float z3 = acc[mi][ni][3] + sBias[n + 1];
            z0 = z0 / (1.f + __expf(-z0));
            z1 = z1 / (1.f + __expf(-z1));
            z2 = z2 / (1.f + __expf(-z2));
            z3 = z3 / (1.f + __expf(-z3));
            uint2 lo = make_uint2(f2tf32(z0), f2tf32(z1));
            uint2 hi = make_uint2(f2tf32(z2), f2tf32(z3));
            *(uint2*)&zb[r * PZ + n]       = lo;
            *(uint2*)&zb[(r + 8) * PZ + n] = hi;
        }
    CP_WAIT0();          // Wu chunk 0 landed
    __syncthreads();

    // ======== Phase 2: U = Z @ Wu  (16 n-chunks of 64, K=64) ========
    // Single SMEM stage W2; next chunk prefetched into REGISTERS (LDG) during compute.
    const float* sW2 = smf + W2 / 4;
    for (int nc = 0; nc < 16; ++nc) {
        float4 pf[8];
        if (nc < 15) {              // issue LDG prefetch of chunk nc+1 (raw fp32)
            const int n0 = (nc + 1) * 64;
#pragma unroll
            for (int i = 0; i < 8; ++i) {
                int lin = i * 128 + tid, kr = lin >> 4, q = (lin & 15) << 2;
                pf[i] = *(const float4*)(wu + (size_t)kr * C_DIM + n0 + q);
            }
        }

        float acc2[4][4][4];
#pragma unroll
        for (int mi = 0; mi < 4; ++mi)
#pragma unroll
            for (int ni = 0; ni < 4; ++ni)
#pragma unroll
                for (int j = 0; j < 4; ++j) acc2[mi][ni][j] = 0.f;

#pragma unroll
        for (int kk = 0; kk < 8; ++kk) {
            const int kb = kk * 8;
            uint32_t a[4][4];
#pragma unroll
            for (int mi = 0; mi < 4; ++mi) {     // Z already tf32 — no cvt
                const uint32_t* ap = zb + (wr + mi * 16 + gr) * PZ + kb + gc;
                a[mi][0] = ap[0];
                a[mi][1] = ap[8 * PZ];
                a[mi][2] = ap[4];
                a[mi][3] = ap[8 * PZ + 4];
            }
#pragma unroll
            for (int ni = 0; ni < 4; ++ni) {
                const float* bp = sW2 + (kb + gc) * PW + wc + ni * 8 + gr;
                uint32_t b0 = f2tf32(bp[0]);
                uint32_t b1 = f2tf32(bp[4 * PW]);
#pragma unroll
                for (int mi = 0; mi < 4; ++mi) mma_tf32(acc2[mi][ni], a[mi], b0, b1);
            }
        }

        const int n0 = nc * 64;
#pragma unroll
        for (int mi = 0; mi < 4; ++mi)
#pragma unroll
            for (int ni = 0; ni < 4; ++ni) {
                int r = wr + mi * 16 + gr;
                int n = n0 + wc + ni * 8 + (gc << 1);
                *(float2*)(oT + (size_t)r * C_DIM + n) =
                    make_float2(acc2[mi][ni][0], acc2[mi][ni][1]);
                *(float2*)(oT + (size_t)(r + 8) * C_DIM + n) =
                    make_float2(acc2[mi][ni][2], acc2[mi][ni][3]);
            }

        if (nc < 15) {              // publish prefetched chunk into W2
            __syncthreads();        // all reads of chunk nc done
#pragma unroll
            for (int i = 0; i < 8; ++i) {
                int lin = i * 128 + tid, kr = lin >> 4, q = (lin & 15) << 2;
                *(float4*)(smf + W2 / 4 + kr * PW + q) = pf[i];
            }
            __syncthreads();        // chunk nc+1 visible to all
        }
    }
}

extern "C" void kernel_launch(void* const* d_in, const int* in_sizes, int n_in,
                              void* d_out, int out_size) {
    const float* x  = (const float*)d_in[0];
    const int*   e  = (const int*)d_in[1];
    const float* dw = (const float*)d_in[2];
    const float* db = (const float*)d_in[3];
    const float* uw = (const float*)d_in[4];

    cudaFuncSetAttribute(adapter_kernel,
                         cudaFuncAttributeMaxDynamicSharedMemorySize, SMEM_BYTES);

    dim3 grid(M_R, B_DIM * (S_DIM / TS));
    adapter_kernel<<<grid, THREADS, SMEM_BYTES>>>(x, e, dw, db, uw, (float*)d_out);
}

// round 12
// speedup vs baseline: 1.3727x; 1.3727x over previous
#include <cuda_runtime.h>
#include <cstdint>

#define M_R   12
#define N_E   8
#define C_DIM 1024
#define D_DIM 64
#define B_DIM 32
#define S_DIM 512
#define TS    128
#define THREADS 128

// smem pitches (words). Bank math (32 banks):
//  A frags (32-wide): pitch 36 -> bank = (4*gr + gc) & 31, distinct over 32 lanes
//  W frags:           pitch 72 -> bank = (8*gc + gr) & 31, distinct
//  Z frags (64-wide): pitch 68 -> bank = (4*gr + gc) & 31, distinct (64 cols need pitch >= 64)
#define PA 36
#define PW 72
#define PZ 68

// dynamic smem byte offsets
// Phase 1: SA0+SA1+SW0+SW1 = 55296
// Phase 2: ZB(34816) + W20/W21 (2x18432) = 73728  (ZB overlays SA0/SA1+part of SW0)
#define SA0 0                         // X stage 0: 128*36*4 = 18432
#define SA1 18432                     // X stage 1
#define SW0 36864                     // Wd stage 0: 32*72*4 = 9216
#define SW1 46080                     // Wd stage 1 (ends 55296)
#define ZB  0                         // Z buffer: 128*68*4 = 34816
#define W20 36864                     // Wu stage 0: 64*72*4 = 18432
#define W21 55296                     // Wu stage 1 (ends 73728)
#define SMEM_BYTES 73856

__device__ __forceinline__ uint32_t smem_u32(const void* p) {
    uint32_t a;
    asm("{ .reg .u64 t; cvta.to.shared.u64 t, %1; cvt.u32.u64 %0, t; }" : "=r"(a) : "l"(p));
    return a;
}
__device__ __forceinline__ uint32_t f2tf32(float f) {
    uint32_t u; asm("cvt.rna.tf32.f32 %0, %1;" : "=r"(u) : "f"(f)); return u;
}
__device__ __forceinline__ void cp16(uint32_t dst, const void* src) {
    asm volatile("cp.async.cg.shared.global [%0], [%1], 16;" :: "r"(dst), "l"(src));
}
#define CP_COMMIT() asm volatile("cp.async.commit_group;" ::: "memory")
#define CP_WAIT0()  asm volatile("cp.async.wait_group 0;" ::: "memory")

__device__ __forceinline__ void mma_tf32(float c[4], const uint32_t a[4],
                                         uint32_t b0, uint32_t b1) {
    asm volatile(
        "mma.sync.aligned.m16n8k8.row.col.f32.tf32.tf32.f32 "
        "{%0,%1,%2,%3}, {%4,%5,%6,%7}, {%8,%9}, {%0,%1,%2,%3};\n"
        : "+f"(c[0]), "+f"(c[1]), "+f"(c[2]), "+f"(c[3])
        : "r"(a[0]), "r"(a[1]), "r"(a[2]), "r"(a[3]), "r"(b0), "r"(b1));
}

__global__ __launch_bounds__(THREADS)
void adapter_kernel(const float* __restrict__ x,
                    const int*   __restrict__ eidx,
                    const float* __restrict__ dw,
                    const float* __restrict__ db,
                    const float* __restrict__ uw,
                    float*       __restrict__ out) {
    extern __shared__ float smf[];
    const uint32_t smb = smem_u32(smf);
    __shared__ float sBias[D_DIM];

    const int tid  = threadIdx.x;
    const int lane = tid & 31;
    const int warp = tid >> 5;
    const int gr   = lane >> 2;         // groupID (row within frag)
    const int gc   = lane & 3;          // thread in group (k/col)
    const int wr   = (warp & 1) * 64;   // warp row offset: 64-row tiles
    const int wc   = (warp >> 1) * 32;  // warp col offset: 32-col tiles

    const int m   = blockIdx.x;         // m fastest -> X tile L2-resident across m
    const int bst = blockIdx.y;
    const int b   = bst >> 2;
    const int st  = bst & 3;

    const int e = eidx[m * B_DIM + b];
    const float* xT = x  + ((size_t)b * S_DIM + (size_t)st * TS) * C_DIM;
    const float* wd = dw + (size_t)(m * N_E + e) * C_DIM * D_DIM;
    const float* wu = uw + (size_t)(m * N_E + e) * D_DIM * C_DIM;
    const float* bb = db + (size_t)(m * N_E + e) * D_DIM;
    float* oT = out + (((size_t)m * B_DIM + b) * S_DIM + (size_t)st * TS) * C_DIM;

    if (tid < D_DIM) sBias[tid] = bb[tid];

    // hoisted staging indices (constant per thread)
    const int xrow = tid >> 3, xq = (tid & 7) << 2;        // X: 8 iters of 16 rows
    const int wkr  = tid >> 4, wq = (tid & 15) << 2;       // W: 4/8 iters

    // hoisted fragment offsets (word offsets, constant per thread)
    const int aOff = (wr + gr) * PA + gc;                  // + mi*16*PA + kb (+4, +8*PA)
    const int bOff = gc * PW + wc + gr;                    // + kb*PW + ni*8 (+4*PW)
    const int zOff = (wr + gr) * PZ + gc;

    float acc[4][4][4];
#pragma unroll
    for (int mi = 0; mi < 4; ++mi)
#pragma unroll
        for (int ni = 0; ni < 4; ++ni)
#pragma unroll
            for (int j = 0; j < 4; ++j) acc[mi][ni][j] = 0.f;

    // -------- prefetch chunk 0 (raw fp32 via cp.async) --------
    {
#pragma unroll
        for (int i = 0; i < 8; ++i) {       // X [128 rows x 32 k]
            int row = i * 16 + xrow;
            cp16(smb + SA0 + (uint32_t)(row * PA + xq) * 4, xT + (size_t)row * C_DIM + xq);
        }
#pragma unroll
        for (int i = 0; i < 4; ++i) {       // Wd [32 k x 64 d]
            int kr = i * 8 + wkr;
            cp16(smb + SW0 + (uint32_t)(kr * PW + wq) * 4, wd + (size_t)kr * D_DIM + wq);
        }
        CP_COMMIT();
    }

    // ================= Phase 1: D1 = X @ Wd  (32 k-chunks of 32) =================
    // one sync per iteration, correctly ordered:
    //   WAIT0 (own copies of chunk kc done) -> SYNC (everyone's copies visible;
    //   all reads of buf cur^1 from iter kc-1 done) -> prefetch kc+1 -> compute kc
    for (int kc = 0; kc < 32; ++kc) {
        const int cur = kc & 1;
        CP_WAIT0();
        __syncthreads();
        if (kc < 31) {
            const int k0 = (kc + 1) * 32;
            const uint32_t na = smb + (cur ? SA0 : SA1);
            const uint32_t nw = smb + (cur ? SW0 : SW1);
#pragma unroll
            for (int i = 0; i < 8; ++i) {
                int row = i * 16 + xrow;
                cp16(na + (uint32_t)(row * PA + xq) * 4, xT + (size_t)row * C_DIM + k0 + xq);
            }
#pragma unroll
            for (int i = 0; i < 4; ++i) {
                int kr = i * 8 + wkr;
                cp16(nw + (uint32_t)(kr * PW + wq) * 4, wd + (size_t)(k0 + kr) * D_DIM + wq);
            }
            CP_COMMIT();
        }
        const float* sA = smf + (cur ? SA1 : SA0) / 4 + aOff;
        const float* sW = smf + (cur ? SW1 : SW0) / 4 + bOff;
#pragma unroll
        for (int kk = 0; kk < 4; ++kk) {
            const int kb = kk * 8;
            uint32_t a[4][4];
#pragma unroll
            for (int mi = 0; mi < 4; ++mi) {
                const float* ap = sA + mi * 16 * PA + kb;
                a[mi][0] = f2tf32(ap[0]);
                a[mi][1] = f2tf32(ap[8 * PA]);
                a[mi][2] = f2tf32(ap[4]);
                a[mi][3] = f2tf32(ap[8 * PA + 4]);
            }
#pragma unroll
            for (int ni = 0; ni < 4; ++ni) {
                const float* bp = sW + kb * PW + ni * 8;
                uint32_t b0 = f2tf32(bp[0]);
                uint32_t b1 = f2tf32(bp[4 * PW]);
#pragma unroll
                for (int mi = 0; mi < 4; ++mi) mma_tf32(acc[mi][ni], a[mi], b0, b1);
            }
        }
    }
    __syncthreads();   // all frag reads done before Z overwrites SA0/SA1

    // prefetch Wu chunk 0 into W20 (overlays dead Wd stages) while epilogue runs
    {
#pragma unroll
        for (int i = 0; i < 8; ++i) {       // Wu [64 d x 64 c]
            int kr = i * 8 + wkr;
            cp16(smb + W20 + (uint32_t)(kr * PW + wq) * 4, wu + (size_t)kr * C_DIM + wq);
        }
        CP_COMMIT();
    }

    // ---- epilogue: Z = swish(D1 + bias) -> zbuf (tf32, pitch 68) ----
    uint32_t* zb = (uint32_t*)smf;
#pragma unroll
    for (int mi = 0; mi < 4; ++mi)
#pragma unroll
        for (int ni = 0; ni < 4; ++ni) {
            int r = wr + mi * 16 + gr;
            int n = wc + ni * 8 + (gc << 1);
            float z0 = acc[mi][ni][0] + sBias[n];
            float z1 = acc[mi][ni][1] + sBias[n + 1];
            float z2 = acc[mi][ni][2] + sBias[n];
            float z3 = acc[mi][ni][3] + sBias[n + 1];
            z0 = z0 / (1.f + __expf(-z0));
            z1 = z1 / (1.f + __expf(-z1));
            z2 = z2 / (1.f + __expf(-z2));
            z3 = z3 / (1.f + __expf(-z3));
            uint2 lo = make_uint2(f2tf32(z0), f2tf32(z1));
            uint2 hi = make_uint2(f2tf32(z2), f2tf32(z3));
            *(uint2*)&zb[r * PZ + n]       = lo;
            *(uint2*)&zb[(r + 8) * PZ + n] = hi;
        }

    // ================= Phase 2: U = Z @ Wu  (16 n-chunks of 64, K=64) =============
    // same one-sync schedule; the iter-0 WAIT0+SYNC also publishes the zb writes
    for (int nc = 0; nc < 16; ++nc) {
        const int cur = nc & 1;
        CP_WAIT0();
        __syncthreads();
        if (nc < 15) {
            const int n0 = (nc + 1) * 64;
            const uint32_t nw = smb + (cur ? W20 : W21);
#pragma unroll
            for (int i = 0; i < 8; ++i) {
                int kr = i * 8 + wkr;
                cp16(nw + (uint32_t)(kr * PW + wq) * 4, wu + (size_t)kr * C_DIM + n0 + wq);
            }
            CP_COMMIT();
        }
        const float* sW = smf + (cur ? W21 : W20) / 4 + bOff;

        float acc2[4][4][4];
#pragma unroll
        for (int mi = 0; mi < 4; ++mi)
#pragma unroll
            for (int ni = 0; ni < 4; ++ni)
#pragma unroll
                for (int j = 0; j < 4; ++j) acc2[mi][ni][j] = 0.f;

#pragma unroll
        for (int kk = 0; kk < 8; ++kk) {
            const int kb = kk * 8;
            uint32_t a[4][4];
#pragma unroll
            for (int mi = 0; mi < 4; ++mi) {     // Z already tf32 — no cvt
                const uint32_t* ap = zb + zOff + mi * 16 * PZ + kb;
                a[mi][0] = ap[0];
                a[mi][1] = ap[8 * PZ];
                a[mi][2] = ap[4];
                a[mi][3] = ap[8 * PZ + 4];
            }
#pragma unroll
            for (int ni = 0; ni < 4; ++ni) {
                const float* bp = sW + kb * PW + ni * 8;
                uint32_t b0 = f2tf32(bp[0]);
                uint32_t b1 = f2tf32(bp[4 * PW]);
#pragma unroll
                for (int mi = 0; mi < 4; ++mi) mma_tf32(acc2[mi][ni], a[mi], b0, b1);
            }
        }

        const int n0 = nc * 64;
#pragma unroll
        for (int mi = 0; mi < 4; ++mi)
#pragma unroll
            for (int ni = 0; ni < 4; ++ni) {
                int r = wr + mi * 16 + gr;
                int n = n0 + wc + ni * 8 + (gc << 1);
                *(float2*)(oT + (size_t)r * C_DIM + n) =
                    make_float2(acc2[mi][ni][0], acc2[mi][ni][1]);
                *(float2*)(oT + (size_t)(r + 8) * C_DIM + n) =
                    make_float2(acc2[mi][ni][2], acc2[mi][ni][3]);
            }
    }
}

extern "C" void kernel_launch(void* const* d_in, const int* in_sizes, int n_in,
                              void* d_out, int out_size) {
    const float* x  = (const float*)d_in[0];
    const int*   e  = (const int*)d_in[1];
    const float* dw = (const float*)d_in[2];
    const float* db = (const float*)d_in[3];
    const float* uw = (const float*)d_in[4];

    cudaFuncSetAttribute(adapter_kernel,
                         cudaFuncAttributeMaxDynamicSharedMemorySize, SMEM_BYTES);

    dim3 grid(M_R, B_DIM * (S_DIM / TS));
    adapter_kernel<<<grid, THREADS, SMEM_BYTES>>>(x, e, dw, db, uw, (float*)d_out);
}